// round 2
// baseline (speedup 1.0000x reference)
#include <cuda_runtime.h>
#include <cstdint>

#define N_NODES 50000
#define C_IN 32
#define HID 64

// Scratch (allocation-free rule: __device__ globals)
__device__ float g_agg0[N_NODES * C_IN];   // 6.4 MB
__device__ float g_agg1[N_NODES * HID];    // 12.8 MB
__device__ float g_h0[N_NODES * HID];      // 12.8 MB
__device__ float g_cnt[N_NODES];

// ---------------------------------------------------------------------------
__global__ void k_zero() {
    int i = blockIdx.x * blockDim.x + threadIdx.x;
    int stride = gridDim.x * blockDim.x;
    for (int j = i; j < N_NODES * C_IN; j += stride) g_agg0[j] = 0.f;
    for (int j = i; j < N_NODES * HID;  j += stride) g_agg1[j] = 0.f;
    for (int j = i; j < N_NODES;        j += stride) g_cnt[j]  = 0.f;
}

// ---------------------------------------------------------------------------
// Layer-0 scatter: 8 threads per edge, each moves a float4 of x[src] into
// agg0[dst] via atomics. Thread q==0 also bumps the edge count for dst.
__global__ void k_scatter0(const float4* __restrict__ x4,
                           const int* __restrict__ ei, int E) {
    int idx = blockIdx.x * blockDim.x + threadIdx.x;
    if (idx >= E * 8) return;
    int e = idx >> 3;
    int q = idx & 7;
    int src = ei[e];
    int dst = ei[E + e];
    float4 v = x4[src * 8 + q];
    float* base = g_agg0 + dst * C_IN + q * 4;
    atomicAdd(base + 0, v.x);
    atomicAdd(base + 1, v.y);
    atomicAdd(base + 2, v.z);
    atomicAdd(base + 3, v.w);
    if (q == 0) atomicAdd(g_cnt + dst, 1.0f);
}

// ---------------------------------------------------------------------------
// Layer-1 scatter: 16 threads per edge, float4 of h0[src] -> agg1[dst].
__global__ void k_scatter1(const int* __restrict__ ei, int E) {
    int idx = blockIdx.x * blockDim.x + threadIdx.x;
    if (idx >= E * 16) return;
    int e = idx >> 4;
    int q = idx & 15;
    int src = ei[e];
    int dst = ei[E + e];
    const float4* h04 = reinterpret_cast<const float4*>(g_h0);
    float4 v = h04[src * 16 + q];
    float* base = g_agg1 + dst * HID + q * 4;
    atomicAdd(base + 0, v.x);
    atomicAdd(base + 1, v.y);
    atomicAdd(base + 2, v.z);
    atomicAdd(base + 3, v.w);
}

// ---------------------------------------------------------------------------
// Layer 0 node update. One warp per node. Lane computes output channels
// {lane, lane+32}. h0 = relu(normalize(mean @ Wl0 + x @ Wr0 + b0)).
__global__ void k_layer0(const float* __restrict__ x,
                         const float* __restrict__ Wl0,
                         const float* __restrict__ b0,
                         const float* __restrict__ Wr0) {
    __shared__ float sWl[C_IN * HID];   // 8 KB
    __shared__ float sWr[C_IN * HID];   // 8 KB
    __shared__ float sb[HID];

    int tid = threadIdx.x;
    for (int j = tid; j < C_IN * HID; j += blockDim.x) { sWl[j] = Wl0[j]; sWr[j] = Wr0[j]; }
    if (tid < HID) sb[tid] = b0[tid];
    __syncthreads();

    int warp = tid >> 5;
    int lane = tid & 31;
    int node = blockIdx.x * 8 + warp;
    if (node >= N_NODES) return;

    float inv_cnt = 1.0f / fmaxf(g_cnt[node], 1.0f);
    float mk_self = g_agg0[node * C_IN + lane] * inv_cnt;  // mean[lane]
    float xk_self = x[node * C_IN + lane];                  // x[lane]

    float acc0 = sb[lane];
    float acc1 = sb[lane + 32];
#pragma unroll
    for (int k = 0; k < C_IN; k++) {
        float mk = __shfl_sync(0xffffffffu, mk_self, k);
        float xk = __shfl_sync(0xffffffffu, xk_self, k);
        acc0 += mk * sWl[k * HID + lane]      + xk * sWr[k * HID + lane];
        acc1 += mk * sWl[k * HID + lane + 32] + xk * sWr[k * HID + lane + 32];
    }

    // L2 row norm across 64 outputs
    float ss = acc0 * acc0 + acc1 * acc1;
#pragma unroll
    for (int off = 16; off > 0; off >>= 1)
        ss += __shfl_xor_sync(0xffffffffu, ss, off);
    float inv = 1.0f / fmaxf(sqrtf(ss), 1e-12f);

    float o0 = fmaxf(acc0 * inv, 0.0f);   // relu after normalize
    float o1 = fmaxf(acc1 * inv, 0.0f);
    g_h0[node * HID + lane]      = o0;
    g_h0[node * HID + lane + 32] = o1;
}

// ---------------------------------------------------------------------------
// Layer 1 node update + classifier, fused. One warp per node.
__global__ void k_layer1(const float* __restrict__ Wl1,
                         const float* __restrict__ b1,
                         const float* __restrict__ Wr1,
                         const float* __restrict__ Wc1,
                         const float* __restrict__ bc1,
                         const float* __restrict__ Wc2,
                         const float* __restrict__ bc2,
                         float* __restrict__ out) {
    __shared__ float sWl[HID * HID];     // 16 KB
    __shared__ float sWr[HID * HID];     // 16 KB
    __shared__ float sb[HID];
    __shared__ float sWc1[HID * 32];     // 8 KB
    __shared__ float sbc1[32];
    __shared__ float sWc2[32];
    __shared__ float sh1[8 * HID];       // per-warp h1 staging

    int tid = threadIdx.x;
    for (int j = tid; j < HID * HID; j += blockDim.x) { sWl[j] = Wl1[j]; sWr[j] = Wr1[j]; }
    for (int j = tid; j < HID * 32; j += blockDim.x) sWc1[j] = Wc1[j];
    if (tid < HID) sb[tid] = b1[tid];
    if (tid < 32) { sbc1[tid] = bc1[tid]; sWc2[tid] = Wc2[tid]; }
    __syncthreads();

    int warp = tid >> 5;
    int lane = tid & 31;
    int node = blockIdx.x * 8 + warp;
    if (node >= N_NODES) return;

    float inv_cnt = 1.0f / fmaxf(g_cnt[node], 1.0f);
    float m_lo = g_agg1[node * HID + lane]      * inv_cnt;
    float m_hi = g_agg1[node * HID + lane + 32] * inv_cnt;
    float h_lo = g_h0[node * HID + lane];
    float h_hi = g_h0[node * HID + lane + 32];

    float acc0 = sb[lane];
    float acc1 = sb[lane + 32];
#pragma unroll
    for (int k = 0; k < 32; k++) {
        float mk = __shfl_sync(0xffffffffu, m_lo, k);
        float hk = __shfl_sync(0xffffffffu, h_lo, k);
        acc0 += mk * sWl[k * HID + lane]      + hk * sWr[k * HID + lane];
        acc1 += mk * sWl[k * HID + lane + 32] + hk * sWr[k * HID + lane + 32];
    }
#pragma unroll
    for (int k = 0; k < 32; k++) {
        int kk = k + 32;
        float mk = __shfl_sync(0xffffffffu, m_hi, k);
        float hk = __shfl_sync(0xffffffffu, h_hi, k);
        acc0 += mk * sWl[kk * HID + lane]      + hk * sWr[kk * HID + lane];
        acc1 += mk * sWl[kk * HID + lane + 32] + hk * sWr[kk * HID + lane + 32];
    }

    float ss = acc0 * acc0 + acc1 * acc1;
#pragma unroll
    for (int off = 16; off > 0; off >>= 1)
        ss += __shfl_xor_sync(0xffffffffu, ss, off);
    float inv = 1.0f / fmaxf(sqrtf(ss), 1e-12f);
    float h1_lo = acc0 * inv;   // no relu on SAGE layer-1 output
    float h1_hi = acc1 * inv;

    // Stage full 64-vector for the classifier GEMV
    sh1[warp * HID + lane]      = h1_lo;
    sh1[warp * HID + lane + 32] = h1_hi;
    __syncwarp();

    // c[lane] = relu(bc1[lane] + sum_k h1[k] * Wc1[k][lane]); logit = sum c*Wc2 + bc2
    float c = sbc1[lane];
    const float* hvec = sh1 + warp * HID;
#pragma unroll
    for (int k = 0; k < HID; k++)
        c += hvec[k] * sWc1[k * 32 + lane];
    c = fmaxf(c, 0.0f);
    float p = c * sWc2[lane];
#pragma unroll
    for (int off = 16; off > 0; off >>= 1)
        p += __shfl_xor_sync(0xffffffffu, p, off);

    if (lane == 0) out[node] = p + bc2[0];
}

// ---------------------------------------------------------------------------
extern "C" void kernel_launch(void* const* d_in, const int* in_sizes, int n_in,
                              void* d_out, int out_size) {
    const float* x    = (const float*)d_in[0];
    const int*   ei   = (const int*)d_in[1];     // JAX x64 disabled -> int32
    const float* Wl0  = (const float*)d_in[2];
    const float* b0   = (const float*)d_in[3];
    const float* Wr0  = (const float*)d_in[4];
    const float* Wl1  = (const float*)d_in[5];
    const float* b1   = (const float*)d_in[6];
    const float* Wr1  = (const float*)d_in[7];
    const float* Wc1  = (const float*)d_in[8];
    const float* bc1  = (const float*)d_in[9];
    const float* Wc2  = (const float*)d_in[10];
    const float* bc2  = (const float*)d_in[11];
    float* out = (float*)d_out;

    int E = in_sizes[1] / 2;   // 1,600,000

    k_zero<<<512, 256>>>();

    int t0 = E * 8;
    k_scatter0<<<(t0 + 255) / 256, 256>>>((const float4*)x, ei, E);

    k_layer0<<<(N_NODES + 7) / 8, 256>>>(x, Wl0, b0, Wr0);

    int t1g = (E * 16 + 255) / 256;
    k_scatter1<<<t1g, 256>>>(ei, E);

    k_layer1<<<(N_NODES + 7) / 8, 256>>>(Wl1, b1, Wr1, Wc1, bc1, Wc2, bc2, out);
}

// round 3
// speedup vs baseline: 1.3727x; 1.3727x over previous
#include <cuda_runtime.h>
#include <cstdint>

#define N_NODES 50000
#define C_IN 32
#define HID 64

// Scratch (allocation-free rule: __device__ globals)
__device__ float g_agg0[N_NODES * C_IN];   // 6.4 MB
__device__ float g_agg1[N_NODES * HID];    // 12.8 MB
__device__ float g_h0[N_NODES * HID];      // 12.8 MB
__device__ float g_cnt[N_NODES];

__device__ __forceinline__ void red_v4(float* p, float4 v) {
    asm volatile("red.global.add.v4.f32 [%0], {%1,%2,%3,%4};"
                 :: "l"(p), "f"(v.x), "f"(v.y), "f"(v.z), "f"(v.w)
                 : "memory");
}

// ---------------------------------------------------------------------------
__global__ void k_zero() {
    int i = blockIdx.x * blockDim.x + threadIdx.x;
    int stride = gridDim.x * blockDim.x;
    for (int j = i; j < N_NODES * C_IN; j += stride) g_agg0[j] = 0.f;
    for (int j = i; j < N_NODES * HID;  j += stride) g_agg1[j] = 0.f;
    for (int j = i; j < N_NODES;        j += stride) g_cnt[j]  = 0.f;
}

// ---------------------------------------------------------------------------
// Layer-0 scatter: 2 threads per edge; each moves 4 float4s (64B) of x[src]
// into agg0[dst] via red.v4. Thread q==0 also bumps the edge count.
__global__ void k_scatter0(const float4* __restrict__ x4,
                           const int* __restrict__ ei, int E) {
    int idx = blockIdx.x * blockDim.x + threadIdx.x;
    if (idx >= E * 2) return;
    int e = idx >> 1;
    int q = idx & 1;
    int src = ei[e];
    int dst = ei[E + e];
    const float4* xs = x4 + src * 8 + q * 4;
    float*        ad = g_agg0 + dst * C_IN + q * 16;
    float4 v0 = xs[0], v1 = xs[1], v2 = xs[2], v3 = xs[3];
    red_v4(ad + 0,  v0);
    red_v4(ad + 4,  v1);
    red_v4(ad + 8,  v2);
    red_v4(ad + 12, v3);
    if (q == 0) atomicAdd(g_cnt + dst, 1.0f);
}

// ---------------------------------------------------------------------------
// Layer-1 scatter: 4 threads per edge; each moves 4 float4s (64B) of h0[src]
// into agg1[dst] via red.v4.
__global__ void k_scatter1(const int* __restrict__ ei, int E) {
    int idx = blockIdx.x * blockDim.x + threadIdx.x;
    if (idx >= E * 4) return;
    int e = idx >> 2;
    int q = idx & 3;
    int src = ei[e];
    int dst = ei[E + e];
    const float4* hs = reinterpret_cast<const float4*>(g_h0) + src * 16 + q * 4;
    float*        ad = g_agg1 + dst * HID + q * 16;
    float4 v0 = hs[0], v1 = hs[1], v2 = hs[2], v3 = hs[3];
    red_v4(ad + 0,  v0);
    red_v4(ad + 4,  v1);
    red_v4(ad + 8,  v2);
    red_v4(ad + 12, v3);
}

// ---------------------------------------------------------------------------
// Layer 0 node update. One warp per node. Lane computes output channels
// {lane, lane+32}. h0 = relu(normalize(mean @ Wl0 + x @ Wr0 + b0)).
__global__ void k_layer0(const float* __restrict__ x,
                         const float* __restrict__ Wl0,
                         const float* __restrict__ b0,
                         const float* __restrict__ Wr0) {
    __shared__ float sWl[C_IN * HID];   // 8 KB
    __shared__ float sWr[C_IN * HID];   // 8 KB
    __shared__ float sb[HID];

    int tid = threadIdx.x;
    for (int j = tid; j < C_IN * HID; j += blockDim.x) { sWl[j] = Wl0[j]; sWr[j] = Wr0[j]; }
    if (tid < HID) sb[tid] = b0[tid];
    __syncthreads();

    int warp = tid >> 5;
    int lane = tid & 31;
    int node = blockIdx.x * 8 + warp;
    if (node >= N_NODES) return;

    float inv_cnt = 1.0f / fmaxf(g_cnt[node], 1.0f);
    float mk_self = g_agg0[node * C_IN + lane] * inv_cnt;  // mean[lane]
    float xk_self = x[node * C_IN + lane];                  // x[lane]

    float acc0 = sb[lane];
    float acc1 = sb[lane + 32];
#pragma unroll
    for (int k = 0; k < C_IN; k++) {
        float mk = __shfl_sync(0xffffffffu, mk_self, k);
        float xk = __shfl_sync(0xffffffffu, xk_self, k);
        acc0 += mk * sWl[k * HID + lane]      + xk * sWr[k * HID + lane];
        acc1 += mk * sWl[k * HID + lane + 32] + xk * sWr[k * HID + lane + 32];
    }

    // L2 row norm across 64 outputs
    float ss = acc0 * acc0 + acc1 * acc1;
#pragma unroll
    for (int off = 16; off > 0; off >>= 1)
        ss += __shfl_xor_sync(0xffffffffu, ss, off);
    float inv = 1.0f / fmaxf(sqrtf(ss), 1e-12f);

    float o0 = fmaxf(acc0 * inv, 0.0f);   // relu after normalize
    float o1 = fmaxf(acc1 * inv, 0.0f);
    g_h0[node * HID + lane]      = o0;
    g_h0[node * HID + lane + 32] = o1;
}

// ---------------------------------------------------------------------------
// Layer 1 node update + classifier, fused. One warp per node.
__global__ void k_layer1(const float* __restrict__ Wl1,
                         const float* __restrict__ b1,
                         const float* __restrict__ Wr1,
                         const float* __restrict__ Wc1,
                         const float* __restrict__ bc1,
                         const float* __restrict__ Wc2,
                         const float* __restrict__ bc2,
                         float* __restrict__ out) {
    __shared__ float sWl[HID * HID];     // 16 KB
    __shared__ float sWr[HID * HID];     // 16 KB
    __shared__ float sb[HID];
    __shared__ float sWc1[HID * 32];     // 8 KB
    __shared__ float sbc1[32];
    __shared__ float sWc2[32];
    __shared__ float sh1[8 * HID];       // per-warp h1 staging

    int tid = threadIdx.x;
    for (int j = tid; j < HID * HID; j += blockDim.x) { sWl[j] = Wl1[j]; sWr[j] = Wr1[j]; }
    for (int j = tid; j < HID * 32; j += blockDim.x) sWc1[j] = Wc1[j];
    if (tid < HID) sb[tid] = b1[tid];
    if (tid < 32) { sbc1[tid] = bc1[tid]; sWc2[tid] = Wc2[tid]; }
    __syncthreads();

    int warp = tid >> 5;
    int lane = tid & 31;
    int node = blockIdx.x * 8 + warp;
    if (node >= N_NODES) return;

    float inv_cnt = 1.0f / fmaxf(g_cnt[node], 1.0f);
    float m_lo = g_agg1[node * HID + lane]      * inv_cnt;
    float m_hi = g_agg1[node * HID + lane + 32] * inv_cnt;
    float h_lo = g_h0[node * HID + lane];
    float h_hi = g_h0[node * HID + lane + 32];

    float acc0 = sb[lane];
    float acc1 = sb[lane + 32];
#pragma unroll
    for (int k = 0; k < 32; k++) {
        float mk = __shfl_sync(0xffffffffu, m_lo, k);
        float hk = __shfl_sync(0xffffffffu, h_lo, k);
        acc0 += mk * sWl[k * HID + lane]      + hk * sWr[k * HID + lane];
        acc1 += mk * sWl[k * HID + lane + 32] + hk * sWr[k * HID + lane + 32];
    }
#pragma unroll
    for (int k = 0; k < 32; k++) {
        int kk = k + 32;
        float mk = __shfl_sync(0xffffffffu, m_hi, k);
        float hk = __shfl_sync(0xffffffffu, h_hi, k);
        acc0 += mk * sWl[kk * HID + lane]      + hk * sWr[kk * HID + lane];
        acc1 += mk * sWl[kk * HID + lane + 32] + hk * sWr[kk * HID + lane + 32];
    }

    float ss = acc0 * acc0 + acc1 * acc1;
#pragma unroll
    for (int off = 16; off > 0; off >>= 1)
        ss += __shfl_xor_sync(0xffffffffu, ss, off);
    float inv = 1.0f / fmaxf(sqrtf(ss), 1e-12f);
    float h1_lo = acc0 * inv;   // no relu on SAGE layer-1 output
    float h1_hi = acc1 * inv;

    // Stage full 64-vector for the classifier GEMV
    sh1[warp * HID + lane]      = h1_lo;
    sh1[warp * HID + lane + 32] = h1_hi;
    __syncwarp();

    // c[lane] = relu(bc1[lane] + sum_k h1[k] * Wc1[k][lane]); logit = sum c*Wc2 + bc2
    float c = sbc1[lane];
    const float* hvec = sh1 + warp * HID;
#pragma unroll
    for (int k = 0; k < HID; k++)
        c += hvec[k] * sWc1[k * 32 + lane];
    c = fmaxf(c, 0.0f);
    float p = c * sWc2[lane];
#pragma unroll
    for (int off = 16; off > 0; off >>= 1)
        p += __shfl_xor_sync(0xffffffffu, p, off);

    if (lane == 0) out[node] = p + bc2[0];
}

// ---------------------------------------------------------------------------
extern "C" void kernel_launch(void* const* d_in, const int* in_sizes, int n_in,
                              void* d_out, int out_size) {
    const float* x    = (const float*)d_in[0];
    const int*   ei   = (const int*)d_in[1];     // int32 edge index
    const float* Wl0  = (const float*)d_in[2];
    const float* b0   = (const float*)d_in[3];
    const float* Wr0  = (const float*)d_in[4];
    const float* Wl1  = (const float*)d_in[5];
    const float* b1   = (const float*)d_in[6];
    const float* Wr1  = (const float*)d_in[7];
    const float* Wc1  = (const float*)d_in[8];
    const float* bc1  = (const float*)d_in[9];
    const float* Wc2  = (const float*)d_in[10];
    const float* bc2  = (const float*)d_in[11];
    float* out = (float*)d_out;

    int E = in_sizes[1] / 2;   // 1,600,000

    k_zero<<<512, 256>>>();

    int t0 = E * 2;
    k_scatter0<<<(t0 + 255) / 256, 256>>>((const float4*)x, ei, E);

    k_layer0<<<(N_NODES + 7) / 8, 256>>>(x, Wl0, b0, Wr0);

    int t1 = E * 4;
    k_scatter1<<<(t1 + 255) / 256, 256>>>(ei, E);

    k_layer1<<<(N_NODES + 7) / 8, 256>>>(Wl1, b1, Wr1, Wc1, bc1, Wc2, bc2, out);
}

// round 5
// speedup vs baseline: 1.9756x; 1.4392x over previous
#include <cuda_runtime.h>
#include <cstdint>

#define N_NODES 50000
#define E_MAX   1600000
#define C_IN 32
#define HID 64
#define SCAN_BLK 1024
#define SCAN_NB  ((N_NODES + SCAN_BLK - 1) / SCAN_BLK)

// Scratch (__device__ globals: allocation-free rule)
__device__ int   g_hist[N_NODES];
__device__ int   g_cursor[N_NODES];
__device__ int   g_rowstart[N_NODES];
__device__ int   g_partials[SCAN_NB];
__device__ int   g_csr_src[E_MAX];
__device__ float g_h0[N_NODES * HID];     // 12.8 MB

// ---------------------------------------------------------------------------
__global__ void k_init() {
    int i = blockIdx.x * blockDim.x + threadIdx.x;
    int stride = gridDim.x * blockDim.x;
    for (int j = i; j < N_NODES; j += stride) { g_hist[j] = 0; g_cursor[j] = 0; }
}

__global__ void k_hist(const int* __restrict__ ei, int E) {
    int e = blockIdx.x * blockDim.x + threadIdx.x;
    if (e >= E) return;
    atomicAdd(g_hist + ei[E + e], 1);
}

// Exclusive scan of g_hist -> g_rowstart (3-phase)
__global__ void k_scan1() {
    __shared__ int sh[SCAN_BLK];
    int gid = blockIdx.x * SCAN_BLK + threadIdx.x;
    int v = (gid < N_NODES) ? g_hist[gid] : 0;
    sh[threadIdx.x] = v;
    __syncthreads();
    for (int off = 1; off < SCAN_BLK; off <<= 1) {
        int t = (threadIdx.x >= off) ? sh[threadIdx.x - off] : 0;
        __syncthreads();
        sh[threadIdx.x] += t;
        __syncthreads();
    }
    if (gid < N_NODES) g_rowstart[gid] = sh[threadIdx.x] - v;   // exclusive
    if (threadIdx.x == SCAN_BLK - 1) g_partials[blockIdx.x] = sh[threadIdx.x];
}

__global__ void k_scan2() {
    if (threadIdx.x == 0) {
        int acc = 0;
        for (int i = 0; i < SCAN_NB; i++) { int t = g_partials[i]; g_partials[i] = acc; acc += t; }
    }
}

__global__ void k_scan3() {
    int gid = blockIdx.x * SCAN_BLK + threadIdx.x;
    if (gid < N_NODES) g_rowstart[gid] += g_partials[blockIdx.x];
}

__global__ void k_fill(const int* __restrict__ ei, int E) {
    int e = blockIdx.x * blockDim.x + threadIdx.x;
    if (e >= E) return;
    int src = ei[e];
    int dst = ei[E + e];
    int pos = g_rowstart[dst] + atomicAdd(g_cursor + dst, 1);
    g_csr_src[pos] = src;
}

// ---------------------------------------------------------------------------
// Layer 0 fused: warp per node. Pull-aggregate mean of x over neighbors
// (lane = channel, coalesced 128B per neighbor), then shuffle-GEMV:
// h0 = relu(normalize(mean @ Wl0 + x @ Wr0 + b0)).
__global__ void k_layer0(const float* __restrict__ x,
                         const float* __restrict__ Wl0,
                         const float* __restrict__ b0,
                         const float* __restrict__ Wr0) {
    __shared__ float sWl[C_IN * HID];   // 8 KB
    __shared__ float sWr[C_IN * HID];   // 8 KB
    __shared__ float sb[HID];

    int tid = threadIdx.x;
    for (int j = tid; j < C_IN * HID; j += blockDim.x) { sWl[j] = Wl0[j]; sWr[j] = Wr0[j]; }
    if (tid < HID) sb[tid] = b0[tid];
    __syncthreads();

    int warp = tid >> 5;
    int lane = tid & 31;
    int node = blockIdx.x * 8 + warp;
    if (node >= N_NODES) return;

    int start = g_rowstart[node];
    int deg   = g_hist[node];

    float sum = 0.0f;
    for (int base = 0; base < deg; base += 32) {
        int nb = 0;
        if (base + lane < deg) nb = g_csr_src[start + base + lane];
        int m = min(32, deg - base);
        int i = 0;
        for (; i + 4 <= m; i += 4) {
            int s0 = __shfl_sync(0xffffffffu, nb, i);
            int s1 = __shfl_sync(0xffffffffu, nb, i + 1);
            int s2 = __shfl_sync(0xffffffffu, nb, i + 2);
            int s3 = __shfl_sync(0xffffffffu, nb, i + 3);
            float p0 = x[s0 * C_IN + lane];
            float p1 = x[s1 * C_IN + lane];
            float p2 = x[s2 * C_IN + lane];
            float p3 = x[s3 * C_IN + lane];
            sum += (p0 + p1) + (p2 + p3);
        }
        for (; i < m; i++) {
            int s = __shfl_sync(0xffffffffu, nb, i);
            sum += x[s * C_IN + lane];
        }
    }
    float inv_cnt = 1.0f / fmaxf((float)deg, 1.0f);
    float mk_self = sum * inv_cnt;             // mean[lane]
    float xk_self = x[node * C_IN + lane];     // x[lane]

    float acc0 = sb[lane];
    float acc1 = sb[lane + 32];
#pragma unroll
    for (int k = 0; k < C_IN; k++) {
        float mk = __shfl_sync(0xffffffffu, mk_self, k);
        float xk = __shfl_sync(0xffffffffu, xk_self, k);
        acc0 += mk * sWl[k * HID + lane]      + xk * sWr[k * HID + lane];
        acc1 += mk * sWl[k * HID + lane + 32] + xk * sWr[k * HID + lane + 32];
    }

    float ss = acc0 * acc0 + acc1 * acc1;
#pragma unroll
    for (int off = 16; off > 0; off >>= 1)
        ss += __shfl_xor_sync(0xffffffffu, ss, off);
    float inv = 1.0f / fmaxf(sqrtf(ss), 1e-12f);

    g_h0[node * HID + lane]      = fmaxf(acc0 * inv, 0.0f);
    g_h0[node * HID + lane + 32] = fmaxf(acc1 * inv, 0.0f);
}

// ---------------------------------------------------------------------------
// Layer 1 fused: warp per node. Pull-aggregate mean of h0 (2 coalesced LDGs
// per neighbor), shuffle-GEMV, normalize, then classifier -> out[node].
__global__ void k_layer1(const float* __restrict__ Wl1,
                         const float* __restrict__ b1,
                         const float* __restrict__ Wr1,
                         const float* __restrict__ Wc1,
                         const float* __restrict__ bc1,
                         const float* __restrict__ Wc2,
                         const float* __restrict__ bc2,
                         float* __restrict__ out) {
    __shared__ float sWl[HID * HID];     // 16 KB
    __shared__ float sWr[HID * HID];     // 16 KB
    __shared__ float sb[HID];
    __shared__ float sWc1[HID * 32];     // 8 KB
    __shared__ float sbc1[32];
    __shared__ float sWc2[32];
    __shared__ float sh1[8 * HID];

    int tid = threadIdx.x;
    for (int j = tid; j < HID * HID; j += blockDim.x) { sWl[j] = Wl1[j]; sWr[j] = Wr1[j]; }
    for (int j = tid; j < HID * 32; j += blockDim.x) sWc1[j] = Wc1[j];
    if (tid < HID) sb[tid] = b1[tid];
    if (tid < 32) { sbc1[tid] = bc1[tid]; sWc2[tid] = Wc2[tid]; }
    __syncthreads();

    int warp = tid >> 5;
    int lane = tid & 31;
    int node = blockIdx.x * 8 + warp;
    if (node >= N_NODES) return;

    int start = g_rowstart[node];
    int deg   = g_hist[node];

    float s_lo = 0.0f, s_hi = 0.0f;
    for (int base = 0; base < deg; base += 32) {
        int nb = 0;
        if (base + lane < deg) nb = g_csr_src[start + base + lane];
        int m = min(32, deg - base);
        int i = 0;
        for (; i + 2 <= m; i += 2) {
            int s0 = __shfl_sync(0xffffffffu, nb, i);
            int s1 = __shfl_sync(0xffffffffu, nb, i + 1);
            float a0 = g_h0[s0 * HID + lane];
            float b0v = g_h0[s0 * HID + 32 + lane];
            float a1 = g_h0[s1 * HID + lane];
            float b1v = g_h0[s1 * HID + 32 + lane];
            s_lo += a0 + a1;
            s_hi += b0v + b1v;
        }
        for (; i < m; i++) {
            int s = __shfl_sync(0xffffffffu, nb, i);
            s_lo += g_h0[s * HID + lane];
            s_hi += g_h0[s * HID + 32 + lane];
        }
    }
    float inv_cnt = 1.0f / fmaxf((float)deg, 1.0f);
    float m_lo = s_lo * inv_cnt;
    float m_hi = s_hi * inv_cnt;
    float h_lo = g_h0[node * HID + lane];
    float h_hi = g_h0[node * HID + 32 + lane];

    float acc0 = sb[lane];
    float acc1 = sb[lane + 32];
#pragma unroll
    for (int k = 0; k < 32; k++) {
        float mk = __shfl_sync(0xffffffffu, m_lo, k);
        float hk = __shfl_sync(0xffffffffu, h_lo, k);
        acc0 += mk * sWl[k * HID + lane]      + hk * sWr[k * HID + lane];
        acc1 += mk * sWl[k * HID + lane + 32] + hk * sWr[k * HID + lane + 32];
    }
#pragma unroll
    for (int k = 0; k < 32; k++) {
        int kk = k + 32;
        float mk = __shfl_sync(0xffffffffu, m_hi, k);
        float hk = __shfl_sync(0xffffffffu, h_hi, k);
        acc0 += mk * sWl[kk * HID + lane]      + hk * sWr[kk * HID + lane];
        acc1 += mk * sWl[kk * HID + lane + 32] + hk * sWr[kk * HID + lane + 32];
    }

    float ss = acc0 * acc0 + acc1 * acc1;
#pragma unroll
    for (int off = 16; off > 0; off >>= 1)
        ss += __shfl_xor_sync(0xffffffffu, ss, off);
    float inv = 1.0f / fmaxf(sqrtf(ss), 1e-12f);
    float h1_lo = acc0 * inv;
    float h1_hi = acc1 * inv;

    sh1[warp * HID + lane]      = h1_lo;
    sh1[warp * HID + lane + 32] = h1_hi;
    __syncwarp();

    float c = sbc1[lane];
    const float* hvec = sh1 + warp * HID;
#pragma unroll
    for (int k = 0; k < HID; k++)
        c += hvec[k] * sWc1[k * 32 + lane];
    c = fmaxf(c, 0.0f);
    float p = c * sWc2[lane];
#pragma unroll
    for (int off = 16; off > 0; off >>= 1)
        p += __shfl_xor_sync(0xffffffffu, p, off);

    if (lane == 0) out[node] = p + bc2[0];
}

// ---------------------------------------------------------------------------
extern "C" void kernel_launch(void* const* d_in, const int* in_sizes, int n_in,
                              void* d_out, int out_size) {
    const float* x    = (const float*)d_in[0];
    const int*   ei   = (const int*)d_in[1];     // int32 edge index
    const float* Wl0  = (const float*)d_in[2];
    const float* b0   = (const float*)d_in[3];
    const float* Wr0  = (const float*)d_in[4];
    const float* Wl1  = (const float*)d_in[5];
    const float* b1   = (const float*)d_in[6];
    const float* Wr1  = (const float*)d_in[7];
    const float* Wc1  = (const float*)d_in[8];
    const float* bc1  = (const float*)d_in[9];
    const float* Wc2  = (const float*)d_in[10];
    const float* bc2  = (const float*)d_in[11];
    float* out = (float*)d_out;

    int E = in_sizes[1] / 2;   // 1,600,000

    k_init<<<128, 256>>>();
    k_hist<<<(E + 255) / 256, 256>>>(ei, E);
    k_scan1<<<SCAN_NB, SCAN_BLK>>>();
    k_scan2<<<1, 32>>>();
    k_scan3<<<SCAN_NB, SCAN_BLK>>>();
    k_fill<<<(E + 255) / 256, 256>>>(ei, E);

    k_layer0<<<(N_NODES + 7) / 8, 256>>>(x, Wl0, b0, Wr0);
    k_layer1<<<(N_NODES + 7) / 8, 256>>>(Wl1, b1, Wr1, Wc1, bc1, Wc2, bc2, out);
}

// round 6
// speedup vs baseline: 1.9759x; 1.0001x over previous
#include <cuda_runtime.h>
#include <cstdint>

#define N_NODES 50000
#define E_MAX   1600000
#define C_IN 32
#define HID 64
#define SCAN_BLK 1024
#define SCAN_NB  ((N_NODES + SCAN_BLK - 1) / SCAN_BLK)
#define FULL 0xffffffffu

// Scratch (__device__ globals: allocation-free rule)
__device__ int   g_hist[N_NODES];
__device__ int   g_cursor[N_NODES];
__device__ int   g_rowstart[N_NODES];
__device__ int   g_partials[SCAN_NB];
__device__ int   g_csr_src[E_MAX];
__device__ float g_h0[N_NODES * HID];     // 12.8 MB

// pick component j (compile-time under full unroll)
#define COMP(v, j) ((j) == 0 ? (v).x : (j) == 1 ? (v).y : (j) == 2 ? (v).z : (v).w)

// ---------------------------------------------------------------------------
__global__ void k_init() {
    int i = blockIdx.x * blockDim.x + threadIdx.x;
    int stride = gridDim.x * blockDim.x;
    for (int j = i; j < N_NODES; j += stride) g_hist[j] = 0;
}

__global__ void k_hist(const int* __restrict__ ei, int E) {
    int e = blockIdx.x * blockDim.x + threadIdx.x;
    if (e >= E) return;
    atomicAdd(g_hist + ei[E + e], 1);
}

// Exclusive scan of g_hist -> g_rowstart (3-phase)
__global__ void k_scan1() {
    __shared__ int sh[SCAN_BLK];
    int gid = blockIdx.x * SCAN_BLK + threadIdx.x;
    int v = (gid < N_NODES) ? g_hist[gid] : 0;
    sh[threadIdx.x] = v;
    __syncthreads();
    for (int off = 1; off < SCAN_BLK; off <<= 1) {
        int t = (threadIdx.x >= off) ? sh[threadIdx.x - off] : 0;
        __syncthreads();
        sh[threadIdx.x] += t;
        __syncthreads();
    }
    if (gid < N_NODES) g_rowstart[gid] = sh[threadIdx.x] - v;   // exclusive
    if (threadIdx.x == SCAN_BLK - 1) g_partials[blockIdx.x] = sh[threadIdx.x];
}

__global__ void k_scan2() {   // exclusive scan of SCAN_NB (<=64) partials
    __shared__ int sh[64];
    int t = threadIdx.x;
    int v = (t < SCAN_NB) ? g_partials[t] : 0;
    sh[t] = v;
    __syncthreads();
    for (int off = 1; off < 64; off <<= 1) {
        int a = (t >= off) ? sh[t - off] : 0;
        __syncthreads();
        sh[t] += a;
        __syncthreads();
    }
    if (t < SCAN_NB) g_partials[t] = sh[t] - v;
}

__global__ void k_scan3() {
    int gid = blockIdx.x * SCAN_BLK + threadIdx.x;
    if (gid < N_NODES) {
        int rs = g_rowstart[gid] + g_partials[blockIdx.x];
        g_rowstart[gid] = rs;
        g_cursor[gid]   = rs;    // seed fill cursor with row start
    }
}

__global__ void k_fill(const int* __restrict__ ei, int E) {
    int e = blockIdx.x * blockDim.x + threadIdx.x;
    if (e >= E) return;
    int src = ei[e];
    int dst = ei[E + e];
    int pos = atomicAdd(g_cursor + dst, 1);
    g_csr_src[pos] = src;
}

// ---------------------------------------------------------------------------
// Layer 0 fused: warp per node. Vectorized pull-aggregation: lane group
// g=lane>>3 handles neighbor i+g, c=lane&7 indexes float4 within the 32-ch
// row -> one LDG.128 covers 4 neighbors. Then shuffle-GEMV:
// h0 = relu(normalize(mean @ Wl0 + x @ Wr0 + b0)).
__global__ void k_layer0(const float4* __restrict__ x4,
                         const float* __restrict__ Wl0,
                         const float* __restrict__ b0,
                         const float* __restrict__ Wr0) {
    __shared__ float sWl[C_IN * HID];   // 8 KB
    __shared__ float sWr[C_IN * HID];   // 8 KB
    __shared__ float sb[HID];

    int tid = threadIdx.x;
    for (int j = tid; j < C_IN * HID; j += blockDim.x) { sWl[j] = Wl0[j]; sWr[j] = Wr0[j]; }
    if (tid < HID) sb[tid] = b0[tid];
    __syncthreads();

    int warp = tid >> 5;
    int lane = tid & 31;
    int node = blockIdx.x * 8 + warp;
    if (node >= N_NODES) return;

    int start = g_rowstart[node];
    int deg   = g_hist[node];

    int g = lane >> 3;     // neighbor sub-group 0..3
    int c = lane & 7;      // float4 index within row

    float a0 = 0.f, a1 = 0.f, a2 = 0.f, a3 = 0.f;
    for (int base = 0; base < deg; base += 32) {
        int nb = 0;
        if (base + lane < deg) nb = g_csr_src[start + base + lane];
        int m = min(32, deg - base);
#pragma unroll
        for (int i = 0; i < 32; i += 4) {
            int take = i + g;
            int s = __shfl_sync(FULL, nb, min(take, m - 1));
            float4 v = x4[s * 8 + c];
            if (take < m) { a0 += v.x; a1 += v.y; a2 += v.z; a3 += v.w; }
            if (i + 4 >= m) break;   // uniform across warp (m warp-uniform)
        }
    }
    // fold the 4 neighbor groups
#pragma unroll
    for (int off = 8; off <= 16; off <<= 1) {
        a0 += __shfl_xor_sync(FULL, a0, off);
        a1 += __shfl_xor_sync(FULL, a1, off);
        a2 += __shfl_xor_sync(FULL, a2, off);
        a3 += __shfl_xor_sync(FULL, a3, off);
    }
    float inv_cnt = 1.0f / fmaxf((float)deg, 1.0f);
    float4 mean4 = make_float4(a0 * inv_cnt, a1 * inv_cnt, a2 * inv_cnt, a3 * inv_cnt);
    float4 self4 = x4[node * 8 + c];   // lanes>=8 hold duplicates; shfl sources 0..7

    float acc0 = sb[lane];
    float acc1 = sb[lane + 32];
#pragma unroll
    for (int k = 0; k < C_IN; k++) {
        int cc = k >> 2, j = k & 3;
        float mk = __shfl_sync(FULL, COMP(mean4, j), cc);
        float xk = __shfl_sync(FULL, COMP(self4, j), cc);
        acc0 += mk * sWl[k * HID + lane]      + xk * sWr[k * HID + lane];
        acc1 += mk * sWl[k * HID + lane + 32] + xk * sWr[k * HID + lane + 32];
    }

    float ss = acc0 * acc0 + acc1 * acc1;
#pragma unroll
    for (int off = 16; off > 0; off >>= 1)
        ss += __shfl_xor_sync(FULL, ss, off);
    float inv = 1.0f / fmaxf(sqrtf(ss), 1e-12f);

    g_h0[node * HID + lane]      = fmaxf(acc0 * inv, 0.0f);
    g_h0[node * HID + lane + 32] = fmaxf(acc1 * inv, 0.0f);
}

// ---------------------------------------------------------------------------
// Layer 1 fused: warp per node. g=lane>>4 handles neighbor i+g, c=lane&15
// indexes float4 within the 64-ch row -> one LDG.128 covers 2 neighbors.
// Shuffle-GEMV, normalize, classifier -> out[node].
__global__ void k_layer1(const float* __restrict__ Wl1,
                         const float* __restrict__ b1,
                         const float* __restrict__ Wr1,
                         const float* __restrict__ Wc1,
                         const float* __restrict__ bc1,
                         const float* __restrict__ Wc2,
                         const float* __restrict__ bc2,
                         float* __restrict__ out) {
    __shared__ float sWl[HID * HID];     // 16 KB
    __shared__ float sWr[HID * HID];     // 16 KB
    __shared__ float sb[HID];
    __shared__ float sWc1[HID * 32];     // 8 KB
    __shared__ float sbc1[32];
    __shared__ float sWc2[32];
    __shared__ float sh1[8 * HID];

    int tid = threadIdx.x;
    for (int j = tid; j < HID * HID; j += blockDim.x) { sWl[j] = Wl1[j]; sWr[j] = Wr1[j]; }
    for (int j = tid; j < HID * 32; j += blockDim.x) sWc1[j] = Wc1[j];
    if (tid < HID) sb[tid] = b1[tid];
    if (tid < 32) { sbc1[tid] = bc1[tid]; sWc2[tid] = Wc2[tid]; }
    __syncthreads();

    int warp = tid >> 5;
    int lane = tid & 31;
    int node = blockIdx.x * 8 + warp;
    if (node >= N_NODES) return;

    int start = g_rowstart[node];
    int deg   = g_hist[node];

    const float4* h04 = reinterpret_cast<const float4*>(g_h0);
    int g = lane >> 4;     // neighbor sub-group 0..1
    int c = lane & 15;     // float4 index within 64-ch row

    float a0 = 0.f, a1 = 0.f, a2 = 0.f, a3 = 0.f;
    for (int base = 0; base < deg; base += 32) {
        int nb = 0;
        if (base + lane < deg) nb = g_csr_src[start + base + lane];
        int m = min(32, deg - base);
#pragma unroll
        for (int i = 0; i < 32; i += 2) {
            int take = i + g;
            int s = __shfl_sync(FULL, nb, min(take, m - 1));
            float4 v = h04[s * 16 + c];
            if (take < m) { a0 += v.x; a1 += v.y; a2 += v.z; a3 += v.w; }
            if (i + 2 >= m) break;   // uniform across warp
        }
    }
    a0 += __shfl_xor_sync(FULL, a0, 16);
    a1 += __shfl_xor_sync(FULL, a1, 16);
    a2 += __shfl_xor_sync(FULL, a2, 16);
    a3 += __shfl_xor_sync(FULL, a3, 16);

    float inv_cnt = 1.0f / fmaxf((float)deg, 1.0f);
    float4 mean4 = make_float4(a0 * inv_cnt, a1 * inv_cnt, a2 * inv_cnt, a3 * inv_cnt);
    float4 self4 = h04[node * 16 + c];

    float acc0 = sb[lane];
    float acc1 = sb[lane + 32];
#pragma unroll
    for (int k = 0; k < HID; k++) {
        int cc = k >> 2, j = k & 3;
        float mk = __shfl_sync(FULL, COMP(mean4, j), cc);
        float hk = __shfl_sync(FULL, COMP(self4, j), cc);
        acc0 += mk * sWl[k * HID + lane]      + hk * sWr[k * HID + lane];
        acc1 += mk * sWl[k * HID + lane + 32] + hk * sWr[k * HID + lane + 32];
    }

    float ss = acc0 * acc0 + acc1 * acc1;
#pragma unroll
    for (int off = 16; off > 0; off >>= 1)
        ss += __shfl_xor_sync(FULL, ss, off);
    float inv = 1.0f / fmaxf(sqrtf(ss), 1e-12f);
    float h1_lo = acc0 * inv;
    float h1_hi = acc1 * inv;

    sh1[warp * HID + lane]      = h1_lo;
    sh1[warp * HID + lane + 32] = h1_hi;
    __syncwarp();

    float cacc = sbc1[lane];
    const float* hvec = sh1 + warp * HID;
#pragma unroll
    for (int k = 0; k < HID; k++)
        cacc += hvec[k] * sWc1[k * 32 + lane];
    cacc = fmaxf(cacc, 0.0f);
    float p = cacc * sWc2[lane];
#pragma unroll
    for (int off = 16; off > 0; off >>= 1)
        p += __shfl_xor_sync(FULL, p, off);

    if (lane == 0) out[node] = p + bc2[0];
}

// ---------------------------------------------------------------------------
extern "C" void kernel_launch(void* const* d_in, const int* in_sizes, int n_in,
                              void* d_out, int out_size) {
    const float* x    = (const float*)d_in[0];
    const int*   ei   = (const int*)d_in[1];     // int32 edge index
    const float* Wl0  = (const float*)d_in[2];
    const float* b0   = (const float*)d_in[3];
    const float* Wr0  = (const float*)d_in[4];
    const float* Wl1  = (const float*)d_in[5];
    const float* b1   = (const float*)d_in[6];
    const float* Wr1  = (const float*)d_in[7];
    const float* Wc1  = (const float*)d_in[8];
    const float* bc1  = (const float*)d_in[9];
    const float* Wc2  = (const float*)d_in[10];
    const float* bc2  = (const float*)d_in[11];
    float* out = (float*)d_out;

    int E = in_sizes[1] / 2;   // 1,600,000

    k_init<<<128, 256>>>();
    k_hist<<<(E + 255) / 256, 256>>>(ei, E);
    k_scan1<<<SCAN_NB, SCAN_BLK>>>();
    k_scan2<<<1, 64>>>();
    k_scan3<<<SCAN_NB, SCAN_BLK>>>();
    k_fill<<<(E + 255) / 256, 256>>>(ei, E);

    k_layer0<<<(N_NODES + 7) / 8, 256>>>((const float4*)x, Wl0, b0, Wr0);
    k_layer1<<<(N_NODES + 7) / 8, 256>>>(Wl1, b1, Wr1, Wc1, bc1, Wc2, bc2, out);
}